// round 5
// baseline (speedup 1.0000x reference)
#include <cuda_runtime.h>
#include <cuda_bf16.h>
#include <cstdint>

#define BB 16
#define CC 768
#define TT 1024
#define STEPS 12
#define NNEG 10
#define COPIES 11
#define BT (BB*TT)  // 16384

// ---- scratch (static device globals; no runtime allocation) ----
__device__ float g_yT[(size_t)BB*TT*CC];                  // [b][t][c]
__device__ float g_proj[(size_t)STEPS*BT*CC];             // [i][m][d]
__device__ __nv_bfloat16 g_xhi[(size_t)BT*CC];            // [m][c]
__device__ __nv_bfloat16 g_xlo[(size_t)BT*CC];
__device__ __nv_bfloat16 g_whi[(size_t)STEPS*CC*CC];      // [(i*768+d)][c]
__device__ __nv_bfloat16 g_wlo[(size_t)STEPS*CC*CC];

// ============================ asm helpers ============================
__device__ __forceinline__ uint32_t smem_u32(const void* p) {
    uint32_t a;
    asm("{ .reg .u64 t; cvta.to.shared.u64 t, %1; cvt.u32.u64 %0, t; }" : "=r"(a) : "l"(p));
    return a;
}

__device__ __forceinline__ void cp_async16(uint32_t saddr, const void* gaddr) {
    asm volatile("cp.async.cg.shared.global [%0], [%1], 16;" :: "r"(saddr), "l"(gaddr));
}
__device__ __forceinline__ void cp_commit() {
    asm volatile("cp.async.commit_group;" ::: "memory");
}
__device__ __forceinline__ void cp_wait1() {
    asm volatile("cp.async.wait_group 1;" ::: "memory");
}

__device__ __forceinline__ void ldmx4(uint32_t* r, uint32_t addr) {
    asm volatile("ldmatrix.sync.aligned.m8n8.x4.shared.b16 {%0,%1,%2,%3}, [%4];"
        : "=r"(r[0]), "=r"(r[1]), "=r"(r[2]), "=r"(r[3]) : "r"(addr));
}

__device__ __forceinline__ void mma16816(float* d, const uint32_t* a, const uint32_t* b) {
    asm volatile("mma.sync.aligned.m16n8k16.row.col.f32.bf16.bf16.f32 "
        "{%0,%1,%2,%3}, {%4,%5,%6,%7}, {%8,%9}, {%0,%1,%2,%3};"
        : "+f"(d[0]), "+f"(d[1]), "+f"(d[2]), "+f"(d[3])
        : "r"(a[0]), "r"(a[1]), "r"(a[2]), "r"(a[3]), "r"(b[0]), "r"(b[1]));
}

// swizzled byte offset for a (row, 16B-chunk) of a [rows][32] bf16 tile
// rows are 64B; two rows share a 128B line; Swizzle<3,4,3> on the line.
__device__ __forceinline__ uint32_t sw_off(int r, int c) {
    uint32_t bo = r*64 + c*16;
    return bo ^ (((bo >> 7) & 7) << 4);
}

// ============================ prepack kernels ============================
__global__ void transpose_y_kernel(const float* __restrict__ y) {
    __shared__ float tile[32][33];
    int b = blockIdx.z, c0 = blockIdx.y * 32, t0 = blockIdx.x * 32;
    int tx = threadIdx.x, ty = threadIdx.y;
    #pragma unroll
    for (int j = 0; j < 32; j += 8)
        tile[ty + j][tx] = y[((size_t)b*CC + c0 + ty + j)*TT + t0 + tx];
    __syncthreads();
    #pragma unroll
    for (int j = 0; j < 32; j += 8)
        g_yT[((size_t)b*TT + t0 + ty + j)*CC + c0 + tx] = tile[tx][ty + j];
}

__global__ void pack_x_kernel(const float* __restrict__ x) {
    __shared__ float tile[32][33];
    int b = blockIdx.z, c0 = blockIdx.y * 32, t0 = blockIdx.x * 32;
    int tx = threadIdx.x, ty = threadIdx.y;
    #pragma unroll
    for (int j = 0; j < 32; j += 8)
        tile[ty + j][tx] = x[((size_t)b*CC + c0 + ty + j)*TT + t0 + tx];
    __syncthreads();
    #pragma unroll
    for (int j = 0; j < 32; j += 8) {
        float v = tile[tx][ty + j];
        __nv_bfloat16 h = __float2bfloat16(v);
        __nv_bfloat16 l = __float2bfloat16(v - __bfloat162float(h));
        size_t o = ((size_t)b*TT + t0 + ty + j)*CC + c0 + tx;
        g_xhi[o] = h;
        g_xlo[o] = l;
    }
}

__global__ void pack_w_kernel(const float* __restrict__ W) {
    size_t o = (size_t)blockIdx.x * blockDim.x + threadIdx.x;
    if (o >= (size_t)STEPS*CC*CC) return;
    int c = (int)(o % CC);
    int d = (int)((o / CC) % CC);
    int i = (int)(o / ((size_t)CC*CC));
    float v = W[((size_t)c*CC + d)*STEPS + i];
    __nv_bfloat16 h = __float2bfloat16(v);
    __nv_bfloat16 l = __float2bfloat16(v - __bfloat162float(h));
    g_whi[o] = h;
    g_wlo[o] = l;
}

// ============================ HMMA GEMM ============================
// Tile 128x64x32, 256 thr (4x2 warps, warp=32x32), 3-stage cp.async,
// bf16x3: hi*hi + hi*lo + lo*hi. 2 CTAs/SM (72KB smem, <=128 regs).
#define BM 128
#define BN 64
#define BK 32
#define KITERS (CC/BK)   // 24
#define SA_L 8192
#define SB_H 16384
#define SB_L 20480
#define STG  24576       // 24KB per stage
#define SMEM_GEMM (3*STG) // 72KB

__global__ __launch_bounds__(256, 2) void gemm_hmma_kernel(const float* __restrict__ bias)
{
    extern __shared__ char smem[];
    const uint32_t sbase = smem_u32(smem);
    const int tid = threadIdx.x;
    const int wid = tid >> 5, lane = tid & 31;
    const int n0 = blockIdx.x * BN;
    const int m0 = blockIdx.y * BM;
    const int stepi = blockIdx.z;
    const int wm = wid >> 1;     // 0..3  (32 rows each)
    const int wn = wid & 1;      // 0..1  (32 cols each)

    const __nv_bfloat16* gAh = g_xhi + (size_t)m0*CC;
    const __nv_bfloat16* gAl = g_xlo + (size_t)m0*CC;
    const __nv_bfloat16* gBh = g_whi + ((size_t)stepi*CC + n0)*CC;
    const __nv_bfloat16* gBl = g_wlo + ((size_t)stepi*CC + n0)*CC;

    auto load_stage = [&](int kt, int s) {
        const int k0 = kt * BK;
        const uint32_t sa = sbase + s*STG;
        #pragma unroll
        for (int e = 0; e < 2; e++) {       // A: 128 rows x 4 chunks
            int idx = tid + e*256;
            int r = idx >> 2, c = idx & 3;
            uint32_t so = sw_off(r, c);
            size_t go = (size_t)r*CC + k0 + c*8;
            cp_async16(sa + so, gAh + go);
            cp_async16(sa + SA_L + so, gAl + go);
        }
        {                                    // B: 64 rows x 4 chunks
            int r = tid >> 2, c = tid & 3;
            uint32_t so = sw_off(r, c);
            size_t go = (size_t)r*CC + k0 + c*8;
            cp_async16(sa + SB_H + so, gBh + go);
            cp_async16(sa + SB_L + so, gBl + go);
        }
        cp_commit();
    };

    float acc[2][4][4];
    #pragma unroll
    for (int mt = 0; mt < 2; mt++)
        #pragma unroll
        for (int nt = 0; nt < 4; nt++)
            #pragma unroll
            for (int q = 0; q < 4; q++) acc[mt][nt][q] = 0.f;

    load_stage(0, 0);
    load_stage(1, 1);

    const int matid = lane >> 3, lrow = lane & 7;

    for (int kt = 0; kt < KITERS; kt++) {
        const int s = kt % 3;
        cp_wait1();
        __syncthreads();
        if (kt + 2 < KITERS) load_stage(kt + 2, (kt + 2) % 3);

        const uint32_t sa = sbase + s*STG;
        #pragma unroll
        for (int h = 0; h < 2; h++) {        // two k16 halves of BK=32
            const int cbase = h*2;
            uint32_t ah[2][4], al[2][4];
            #pragma unroll
            for (int mt = 0; mt < 2; mt++) {
                int m = wm*32 + mt*16 + ((matid & 1) ? 8 : 0) + lrow;
                int c = cbase + (matid >> 1);
                uint32_t so = sw_off(m, c);
                ldmx4(ah[mt], sa + so);
                ldmx4(al[mt], sa + SA_L + so);
            }
            uint32_t bh[2][4], bl[2][4];
            #pragma unroll
            for (int np = 0; np < 2; np++) {
                int n = wn*32 + np*16 + ((matid >> 1) ? 8 : 0) + lrow;
                int c = cbase + (matid & 1);
                uint32_t so = sw_off(n, c);
                ldmx4(bh[np], sa + SB_H + so);
                ldmx4(bl[np], sa + SB_L + so);
            }
            #pragma unroll
            for (int mt = 0; mt < 2; mt++)
                #pragma unroll
                for (int nt = 0; nt < 4; nt++) {
                    const uint32_t* fh = &bh[nt >> 1][(nt & 1)*2];
                    const uint32_t* fl = &bl[nt >> 1][(nt & 1)*2];
                    mma16816(acc[mt][nt], ah[mt], fh);
                    mma16816(acc[mt][nt], ah[mt], fl);
                    mma16816(acc[mt][nt], al[mt], fh);
                }
        }
    }

    // epilogue
    const int mrow = wm*32 + (lane >> 2);
    const int ncol = wn*32 + (lane & 3)*2;
    #pragma unroll
    for (int nt = 0; nt < 4; nt++) {
        const int col = ncol + nt*8;
        const float b0 = bias[n0 + col], b1 = bias[n0 + col + 1];
        #pragma unroll
        for (int mt = 0; mt < 2; mt++) {
            float* o = g_proj + ((size_t)stepi*BT + m0 + mrow + mt*16)*CC + n0 + col;
            *reinterpret_cast<float2*>(o) =
                make_float2(acc[mt][nt][0] + b0, acc[mt][nt][1] + b1);
            *reinterpret_cast<float2*>(o + 8*CC) =
                make_float2(acc[mt][nt][2] + b0, acc[mt][nt][3] + b1);
        }
    }
}

// ============================ logits dot kernel ============================
// One block per (b, t2): the same 11 targets serve all 12 prediction steps.
// smem: targets [11][768] + proj rows [12][768] fp32. 4 warps x 3 steps each.
#define DOT_SMEM ((11 + 12) * CC * 4)   // 70656 bytes

__global__ __launch_bounds__(128) void dot2_kernel(
    const int* __restrict__ neg, float* __restrict__ outp)
{
    extern __shared__ float ds[];
    float4* sT = reinterpret_cast<float4*>(ds);              // [11][192]
    float4* sP = reinterpret_cast<float4*>(ds + 11*CC);      // [12][192]
    const int b  = blockIdx.y;
    const int t2 = blockIdx.x + 1;        // 1..1023
    const int tid = threadIdx.x;
    const int nvalid = (t2 < STEPS) ? t2 : STEPS;

    const float4* yT4 = reinterpret_cast<const float4*>(g_yT);
    const float4* pj4 = reinterpret_cast<const float4*>(g_proj);

    // load 11 target rows
    for (int idx = tid; idx < 11*192; idx += 128) {
        int row = idx / 192, q = idx - row*192;
        int src = (row == 0) ? (b*TT + t2) : neg[b*(NNEG*TT) + (row-1)*TT + t2];
        sT[row*192 + q] = yT4[(size_t)src*192 + q];
    }
    // load valid proj rows (step i pairs with t = t2-1-i)
    for (int idx = tid; idx < 12*192; idx += 128) {
        int i = idx / 192, q = idx - i*192;
        if (i < nvalid) {
            int t = t2 - 1 - i;
            sP[i*192 + q] = pj4[((size_t)i*BT + (size_t)b*TT + t)*192 + q];
        }
    }
    __syncthreads();

    const int wid = tid >> 5, lane = tid & 31;
    float acc[3][COPIES];
    #pragma unroll
    for (int j = 0; j < 3; j++)
        #pragma unroll
        for (int n = 0; n < COPIES; n++) acc[j][n] = 0.f;

    #pragma unroll
    for (int q = lane, it = 0; it < 192/32; q += 32, it++) {
        float4 tv[COPIES];
        #pragma unroll
        for (int n = 0; n < COPIES; n++) tv[n] = sT[n*192 + q];
        #pragma unroll
        for (int j = 0; j < 3; j++) {
            float4 pv = sP[(wid*3 + j)*192 + q];
            #pragma unroll
            for (int n = 0; n < COPIES; n++)
                acc[j][n] += pv.x*tv[n].x + pv.y*tv[n].y + pv.z*tv[n].z + pv.w*tv[n].w;
        }
    }

    #pragma unroll
    for (int j = 0; j < 3; j++) {
        #pragma unroll
        for (int n = 0; n < COPIES; n++)
            #pragma unroll
            for (int s = 16; s > 0; s >>= 1)
                acc[j][n] += __shfl_xor_sync(0xffffffffu, acc[j][n], s);
        const int i = wid*3 + j;
        if (i < nvalid && lane == 0) {
            const int t = t2 - 1 - i;
            const int off = 16*(1023*i - (i*(i-1))/2);
            float* o = outp + (size_t)(off + t*BB + b)*COPIES;
            #pragma unroll
            for (int n = 0; n < COPIES; n++) o[n] = acc[j][n];
        }
    }
}

// ============================ host ============================
extern "C" void kernel_launch(void* const* d_in, const int* in_sizes, int n_in,
                              void* d_out, int out_size) {
    const float* x    = (const float*)d_in[0];
    const float* y    = (const float*)d_in[1];
    const float* W    = (const float*)d_in[2];
    const float* bias = (const float*)d_in[3];
    const int*   neg  = (const int*)d_in[4];
    float* out = (float*)d_out;

    int total_rows = 0;
    for (int i = 0; i < STEPS; i++) total_rows += (TT - 1 - i) * BB;  // 195360
    size_t npred = (size_t)total_rows * COPIES;

    if ((size_t)out_size > npred)
        cudaMemsetAsync((char*)d_out + npred * 4, 0, ((size_t)out_size - npred) * 4);

    static bool attr_set = false;
    if (!attr_set) {
        cudaFuncSetAttribute(gemm_hmma_kernel,
                             cudaFuncAttributeMaxDynamicSharedMemorySize, SMEM_GEMM);
        cudaFuncSetAttribute(dot2_kernel,
                             cudaFuncAttributeMaxDynamicSharedMemorySize, DOT_SMEM);
        attr_set = true;
    }

    {   // y transpose (for dot kernel)
        dim3 g(TT/32, CC/32, BB), blk(32, 8);
        transpose_y_kernel<<<g, blk>>>(y);
    }
    {   // x pack (bf16 hi/lo, transposed)
        dim3 g(TT/32, CC/32, BB), blk(32, 8);
        pack_x_kernel<<<g, blk>>>(x);
    }
    {   // W pack
        size_t n = (size_t)STEPS*CC*CC;
        pack_w_kernel<<<(unsigned)((n + 255)/256), 256>>>(W);
    }
    {   // HMMA GEMM
        dim3 g(CC/BN, BT/BM, STEPS);   // (12, 128, 12)
        gemm_hmma_kernel<<<g, 256, SMEM_GEMM>>>(bias);
    }
    {   // logits
        dim3 g(TT-1, BB);              // (1023, 16)
        dot2_kernel<<<g, 128, DOT_SMEM>>>(neg, out);
    }
}

// round 7
// speedup vs baseline: 1.1643x; 1.1643x over previous
#include <cuda_runtime.h>
#include <cuda_fp16.h>
#include <cstdint>

#define BB 16
#define CC 768
#define TT 1024
#define STEPS 12
#define NNEG 10
#define COPIES 11
#define BT (BB*TT)  // 16384

// ---- scratch (static device globals; no runtime allocation) ----
__device__ float g_yT[(size_t)BB*TT*CC];          // [b][t][c]
__device__ float g_proj[(size_t)STEPS*BT*CC];     // [i][m][d]
__device__ __half g_xh[(size_t)BT*CC];            // [m][c]
__device__ __half g_xl[(size_t)BT*CC];
__device__ __half g_wh[(size_t)STEPS*CC*CC];      // [(i*768+d)][c]

// ============================ asm helpers ============================
__device__ __forceinline__ uint32_t smem_u32(const void* p) {
    uint32_t a;
    asm("{ .reg .u64 t; cvta.to.shared.u64 t, %1; cvt.u32.u64 %0, t; }" : "=r"(a) : "l"(p));
    return a;
}

__device__ __forceinline__ void cp_async16(uint32_t saddr, const void* gaddr) {
    asm volatile("cp.async.cg.shared.global [%0], [%1], 16;" :: "r"(saddr), "l"(gaddr));
}
__device__ __forceinline__ void cp_commit() {
    asm volatile("cp.async.commit_group;" ::: "memory");
}
__device__ __forceinline__ void cp_wait1() {
    asm volatile("cp.async.wait_group 1;" ::: "memory");
}

__device__ __forceinline__ void ldmx4(uint32_t* r, uint32_t addr) {
    asm volatile("ldmatrix.sync.aligned.m8n8.x4.shared.b16 {%0,%1,%2,%3}, [%4];"
        : "=r"(r[0]), "=r"(r[1]), "=r"(r[2]), "=r"(r[3]) : "r"(addr));
}

__device__ __forceinline__ void mma16816(float* d, const uint32_t* a, const uint32_t* b) {
    asm volatile("mma.sync.aligned.m16n8k16.row.col.f32.f16.f16.f32 "
        "{%0,%1,%2,%3}, {%4,%5,%6,%7}, {%8,%9}, {%0,%1,%2,%3};"
        : "+f"(d[0]), "+f"(d[1]), "+f"(d[2]), "+f"(d[3])
        : "r"(a[0]), "r"(a[1]), "r"(a[2]), "r"(a[3]), "r"(b[0]), "r"(b[1]));
}

// swizzled byte offset for a (row, 16B-chunk) of a [rows][32] fp16 tile
// rows are 64B; two rows share a 128B line; Swizzle<3,4,3> on the line.
__device__ __forceinline__ uint32_t sw_off(int r, int c) {
    uint32_t bo = r*64 + c*16;
    return bo ^ (((bo >> 7) & 7) << 4);
}

// ============================ prepack kernels ============================
__global__ void transpose_y_kernel(const float* __restrict__ y) {
    __shared__ float tile[32][33];
    int b = blockIdx.z, c0 = blockIdx.y * 32, t0 = blockIdx.x * 32;
    int tx = threadIdx.x, ty = threadIdx.y;
    #pragma unroll
    for (int j = 0; j < 32; j += 8)
        tile[ty + j][tx] = y[((size_t)b*CC + c0 + ty + j)*TT + t0 + tx];
    __syncthreads();
    #pragma unroll
    for (int j = 0; j < 32; j += 8)
        g_yT[((size_t)b*TT + t0 + ty + j)*CC + c0 + tx] = tile[tx][ty + j];
}

__global__ void pack_x_kernel(const float* __restrict__ x) {
    __shared__ float tile[32][33];
    int b = blockIdx.z, c0 = blockIdx.y * 32, t0 = blockIdx.x * 32;
    int tx = threadIdx.x, ty = threadIdx.y;
    #pragma unroll
    for (int j = 0; j < 32; j += 8)
        tile[ty + j][tx] = x[((size_t)b*CC + c0 + ty + j)*TT + t0 + tx];
    __syncthreads();
    #pragma unroll
    for (int j = 0; j < 32; j += 8) {
        float v = tile[tx][ty + j];
        __half h = __float2half_rn(v);
        __half l = __float2half_rn(v - __half2float(h));
        size_t o = ((size_t)b*TT + t0 + ty + j)*CC + c0 + tx;
        g_xh[o] = h;
        g_xl[o] = l;
    }
}

__global__ void pack_w_kernel(const float* __restrict__ W) {
    size_t o = (size_t)blockIdx.x * blockDim.x + threadIdx.x;
    if (o >= (size_t)STEPS*CC*CC) return;
    int c = (int)(o % CC);
    int d = (int)((o / CC) % CC);
    int i = (int)(o / ((size_t)CC*CC));
    g_wh[o] = __float2half_rn(W[((size_t)c*CC + d)*STEPS + i]);
}

// ============================ HMMA GEMM ============================
// Round-4 proven structure, fp16 2-pass: proj = xh*w + xl*w (+bias).
// Tile 128x128x32, 256 thr (2x4 warps, warp=64x32), 3-stage cp.async.
#define BM 128
#define BN 128
#define BK 32
#define KITERS (CC/BK)   // 24
#define TILE_B (BM*BK*2) // 8192 bytes per sub-tile
#define SA_H 0
#define SA_L (TILE_B)
#define SB_H (2*TILE_B)
#define STG  (3*TILE_B)  // 24576 per stage
#define SMEM_GEMM (3*STG) // 73728

__global__ __launch_bounds__(256, 1) void gemm_hmma_kernel(const float* __restrict__ bias)
{
    extern __shared__ char smem[];
    const uint32_t sbase = smem_u32(smem);
    const int tid = threadIdx.x;
    const int wid = tid >> 5, lane = tid & 31;
    const int n0 = blockIdx.x * BN;
    const int m0 = blockIdx.y * BM;
    const int stepi = blockIdx.z;
    const int wm = wid >> 2;     // 0..1
    const int wn = wid & 3;      // 0..3

    const __half* gAh = g_xh + (size_t)m0*CC;
    const __half* gAl = g_xl + (size_t)m0*CC;
    const __half* gB  = g_wh + ((size_t)stepi*CC + n0)*CC;

    // per-thread load slots: idx = tid + e*256; r = idx/4 (row), c = idx%4 (16B chunk)
    const int lr0 = tid >> 2, lc = tid & 3;

    auto load_stage = [&](int kt, int s) {
        const int k0 = kt * BK;
        const uint32_t sa = sbase + s*STG;
        #pragma unroll
        for (int e = 0; e < 2; e++) {
            int r = lr0 + e*64;
            uint32_t so = sw_off(r, lc);
            size_t go = (size_t)r*CC + k0 + lc*8;
            cp_async16(sa + SA_H + so, gAh + go);
            cp_async16(sa + SA_L + so, gAl + go);
            cp_async16(sa + SB_H + so, gB + go);
        }
        cp_commit();
    };

    float acc[4][4][4];
    #pragma unroll
    for (int mt = 0; mt < 4; mt++)
        #pragma unroll
        for (int nt = 0; nt < 4; nt++)
            #pragma unroll
            for (int q = 0; q < 4; q++) acc[mt][nt][q] = 0.f;

    load_stage(0, 0);
    load_stage(1, 1);

    const int matid = lane >> 3, lrow = lane & 7;

    for (int kt = 0; kt < KITERS; kt++) {
        const int s = kt % 3;
        cp_wait1();
        __syncthreads();
        if (kt + 2 < KITERS) load_stage(kt + 2, (kt + 2) % 3);

        const uint32_t sa = sbase + s*STG;
        #pragma unroll
        for (int h = 0; h < 2; h++) {          // two k16 halves of BK=32
            const int cbase = h*2;
            uint32_t ah[4][4], al[4][4];
            #pragma unroll
            for (int mt = 0; mt < 4; mt++) {
                int m = wm*64 + mt*16 + ((matid & 1) ? 8 : 0) + lrow;
                int c = cbase + (matid >> 1);
                uint32_t so = sw_off(m, c);
                ldmx4(ah[mt], sa + SA_H + so);
                ldmx4(al[mt], sa + SA_L + so);
            }
            uint32_t bf[2][4];
            #pragma unroll
            for (int np = 0; np < 2; np++) {
                int n = wn*32 + np*16 + ((matid >> 1) ? 8 : 0) + lrow;
                int c = cbase + (matid & 1);
                uint32_t so = sw_off(n, c);
                ldmx4(bf[np], sa + SB_H + so);
            }
            #pragma unroll
            for (int mt = 0; mt < 4; mt++)
                #pragma unroll
                for (int nt = 0; nt < 4; nt++) {
                    const uint32_t* f = &bf[nt >> 1][(nt & 1)*2];
                    mma16816(acc[mt][nt], ah[mt], f);
                    mma16816(acc[mt][nt], al[mt], f);
                }
        }
    }

    // epilogue: d0,d1 -> (row, col..col+1); d2,d3 -> (row+8, col..col+1)
    const int mrow = wm*64 + (lane >> 2);
    const int ncol = wn*32 + (lane & 3)*2;
    #pragma unroll
    for (int nt = 0; nt < 4; nt++) {
        const int col = ncol + nt*8;
        const float b0 = bias[n0 + col], b1 = bias[n0 + col + 1];
        #pragma unroll
        for (int mt = 0; mt < 4; mt++) {
            float* o = g_proj + ((size_t)stepi*BT + m0 + mrow + mt*16)*CC + n0 + col;
            *reinterpret_cast<float2*>(o) =
                make_float2(acc[mt][nt][0] + b0, acc[mt][nt][1] + b1);
            *reinterpret_cast<float2*>(o + 8*CC) =
                make_float2(acc[mt][nt][2] + b0, acc[mt][nt][3] + b1);
        }
    }
}

// ============================ logits dot kernel ============================
// One block per (b, t2): the same 11 targets serve all 12 prediction steps.
// smem: targets [11][768] + proj rows [12][768] fp32. 4 warps x 3 steps each.
#define DOT_SMEM ((11 + 12) * CC * 4)   // 70656 bytes

__global__ __launch_bounds__(128) void dot2_kernel(
    const int* __restrict__ neg, float* __restrict__ outp)
{
    extern __shared__ float ds[];
    float4* sT = reinterpret_cast<float4*>(ds);              // [11][192]
    float4* sP = reinterpret_cast<float4*>(ds + 11*CC);      // [12][192]
    const int b  = blockIdx.y;
    const int t2 = blockIdx.x + 1;        // 1..1023
    const int tid = threadIdx.x;
    const int nvalid = (t2 < STEPS) ? t2 : STEPS;

    const float4* yT4 = reinterpret_cast<const float4*>(g_yT);
    const float4* pj4 = reinterpret_cast<const float4*>(g_proj);

    // load 11 target rows
    for (int idx = tid; idx < 11*192; idx += 128) {
        int row = idx / 192, q = idx - row*192;
        int src = (row == 0) ? (b*TT + t2) : neg[b*(NNEG*TT) + (row-1)*TT + t2];
        sT[row*192 + q] = yT4[(size_t)src*192 + q];
    }
    // load valid proj rows (step i pairs with t = t2-1-i)
    for (int idx = tid; idx < 12*192; idx += 128) {
        int i = idx / 192, q = idx - i*192;
        if (i < nvalid) {
            int t = t2 - 1 - i;
            sP[i*192 + q] = pj4[((size_t)i*BT + (size_t)b*TT + t)*192 + q];
        }
    }
    __syncthreads();

    const int wid = tid >> 5, lane = tid & 31;
    float acc[3][COPIES];
    #pragma unroll
    for (int j = 0; j < 3; j++)
        #pragma unroll
        for (int n = 0; n < COPIES; n++) acc[j][n] = 0.f;

    #pragma unroll
    for (int q = lane, it = 0; it < 192/32; q += 32, it++) {
        float4 tv[COPIES];
        #pragma unroll
        for (int n = 0; n < COPIES; n++) tv[n] = sT[n*192 + q];
        #pragma unroll
        for (int j = 0; j < 3; j++) {
            float4 pv = sP[(wid*3 + j)*192 + q];
            #pragma unroll
            for (int n = 0; n < COPIES; n++)
                acc[j][n] += pv.x*tv[n].x + pv.y*tv[n].y + pv.z*tv[n].z + pv.w*tv[n].w;
        }
    }

    #pragma unroll
    for (int j = 0; j < 3; j++) {
        #pragma unroll
        for (int n = 0; n < COPIES; n++)
            #pragma unroll
            for (int s = 16; s > 0; s >>= 1)
                acc[j][n] += __shfl_xor_sync(0xffffffffu, acc[j][n], s);
        const int i = wid*3 + j;
        if (i < nvalid && lane == 0) {
            const int t = t2 - 1 - i;
            const int off = 16*(1023*i - (i*(i-1))/2);
            float* o = outp + (size_t)(off + t*BB + b)*COPIES;
            #pragma unroll
            for (int n = 0; n < COPIES; n++) o[n] = acc[j][n];
        }
    }
}

// ============================ host ============================
extern "C" void kernel_launch(void* const* d_in, const int* in_sizes, int n_in,
                              void* d_out, int out_size) {
    const float* x    = (const float*)d_in[0];
    const float* y    = (const float*)d_in[1];
    const float* W    = (const float*)d_in[2];
    const float* bias = (const float*)d_in[3];
    const int*   neg  = (const int*)d_in[4];
    float* out = (float*)d_out;

    int total_rows = 0;
    for (int i = 0; i < STEPS; i++) total_rows += (TT - 1 - i) * BB;  // 195360
    size_t npred = (size_t)total_rows * COPIES;

    if ((size_t)out_size > npred)
        cudaMemsetAsync((char*)d_out + npred * 4, 0, ((size_t)out_size - npred) * 4);

    static bool attr_set = false;
    if (!attr_set) {
        cudaFuncSetAttribute(gemm_hmma_kernel,
                             cudaFuncAttributeMaxDynamicSharedMemorySize, SMEM_GEMM);
        cudaFuncSetAttribute(dot2_kernel,
                             cudaFuncAttributeMaxDynamicSharedMemorySize, DOT_SMEM);
        attr_set = true;
    }

    {   // y transpose
        dim3 g(TT/32, CC/32, BB), blk(32, 8);
        transpose_y_kernel<<<g, blk>>>(y);
    }
    {   // x pack (fp16 hi/lo, transposed)
        dim3 g(TT/32, CC/32, BB), blk(32, 8);
        pack_x_kernel<<<g, blk>>>(x);
    }
    {   // W pack (fp16 single)
        size_t n = (size_t)STEPS*CC*CC;
        pack_w_kernel<<<(unsigned)((n + 255)/256), 256>>>(W);
    }
    {   // HMMA GEMM
        dim3 g(CC/BN, BT/BM, STEPS);   // (6, 128, 12)
        gemm_hmma_kernel<<<g, 256, SMEM_GEMM>>>(bias);
    }
    {   // logits
        dim3 g(TT-1, BB);              // (1023, 16)
        dot2_kernel<<<g, 128, DOT_SMEM>>>(neg, out);
    }
}

// round 8
// speedup vs baseline: 1.2990x; 1.1158x over previous
#include <cuda_runtime.h>
#include <cuda_fp16.h>
#include <cstdint>

#define BB 16
#define CC 768
#define TT 1024
#define STEPS 12
#define NNEG 10
#define COPIES 11
#define BT (BB*TT)  // 16384

// ---- scratch (static device globals; no runtime allocation) ----
__device__ float g_yT[(size_t)BB*TT*CC];          // [b][t][c]
__device__ __half g_projh[(size_t)STEPS*BT*CC];   // [i][m][d]  fp16 (302 MB)
__device__ __half g_xh[(size_t)BT*CC];            // [m][c]
__device__ __half g_xl[(size_t)BT*CC];
__device__ __half g_wh[(size_t)STEPS*CC*CC];      // [(i*768+d)][c]

// ============================ asm helpers ============================
__device__ __forceinline__ uint32_t smem_u32(const void* p) {
    uint32_t a;
    asm("{ .reg .u64 t; cvta.to.shared.u64 t, %1; cvt.u32.u64 %0, t; }" : "=r"(a) : "l"(p));
    return a;
}

__device__ __forceinline__ void cp_async16(uint32_t saddr, const void* gaddr) {
    asm volatile("cp.async.cg.shared.global [%0], [%1], 16;" :: "r"(saddr), "l"(gaddr));
}
__device__ __forceinline__ void cp_commit() {
    asm volatile("cp.async.commit_group;" ::: "memory");
}
__device__ __forceinline__ void cp_wait2() {
    asm volatile("cp.async.wait_group 2;" ::: "memory");
}

__device__ __forceinline__ void ldmx4(uint32_t* r, uint32_t addr) {
    asm volatile("ldmatrix.sync.aligned.m8n8.x4.shared.b16 {%0,%1,%2,%3}, [%4];"
        : "=r"(r[0]), "=r"(r[1]), "=r"(r[2]), "=r"(r[3]) : "r"(addr));
}

__device__ __forceinline__ void mma16816(float* d, const uint32_t* a, const uint32_t* b) {
    asm volatile("mma.sync.aligned.m16n8k16.row.col.f32.f16.f16.f32 "
        "{%0,%1,%2,%3}, {%4,%5,%6,%7}, {%8,%9}, {%0,%1,%2,%3};"
        : "+f"(d[0]), "+f"(d[1]), "+f"(d[2]), "+f"(d[3])
        : "r"(a[0]), "r"(a[1]), "r"(a[2]), "r"(a[3]), "r"(b[0]), "r"(b[1]));
}

// swizzled byte offset for a (row, 16B-chunk) of a [rows][32] fp16 tile
__device__ __forceinline__ uint32_t sw_off(int r, int c) {
    uint32_t bo = r*64 + c*16;
    return bo ^ (((bo >> 7) & 7) << 4);
}

// ============================ prepack kernels ============================
__global__ void transpose_y_kernel(const float* __restrict__ y) {
    __shared__ float tile[32][33];
    int b = blockIdx.z, c0 = blockIdx.y * 32, t0 = blockIdx.x * 32;
    int tx = threadIdx.x, ty = threadIdx.y;
    #pragma unroll
    for (int j = 0; j < 32; j += 8)
        tile[ty + j][tx] = y[((size_t)b*CC + c0 + ty + j)*TT + t0 + tx];
    __syncthreads();
    #pragma unroll
    for (int j = 0; j < 32; j += 8)
        g_yT[((size_t)b*TT + t0 + ty + j)*CC + c0 + tx] = tile[tx][ty + j];
}

__global__ void pack_x_kernel(const float* __restrict__ x) {
    __shared__ float tile[32][33];
    int b = blockIdx.z, c0 = blockIdx.y * 32, t0 = blockIdx.x * 32;
    int tx = threadIdx.x, ty = threadIdx.y;
    #pragma unroll
    for (int j = 0; j < 32; j += 8)
        tile[ty + j][tx] = x[((size_t)b*CC + c0 + ty + j)*TT + t0 + tx];
    __syncthreads();
    #pragma unroll
    for (int j = 0; j < 32; j += 8) {
        float v = tile[tx][ty + j];
        __half h = __float2half_rn(v);
        __half l = __float2half_rn(v - __half2float(h));
        size_t o = ((size_t)b*TT + t0 + ty + j)*CC + c0 + tx;
        g_xh[o] = h;
        g_xl[o] = l;
    }
}

__global__ void pack_w_kernel(const float* __restrict__ W) {
    size_t o = (size_t)blockIdx.x * blockDim.x + threadIdx.x;
    if (o >= (size_t)STEPS*CC*CC) return;
    int c = (int)(o % CC);
    int d = (int)((o / CC) % CC);
    int i = (int)(o / ((size_t)CC*CC));
    g_wh[o] = __float2half_rn(W[((size_t)c*CC + d)*STEPS + i]);
}

// ============================ HMMA GEMM ============================
// fp16 2-pass: proj = xh*w + xl*w (+bias), output fp16.
// Tile 128x128x32, 256 thr (2x4 warps, warp=64x32), 4-stage cp.async.
#define BM 128
#define BN 128
#define BK 32
#define KITERS (CC/BK)   // 24
#define TILE_B (BM*BK*2) // 8192 bytes per sub-tile
#define SA_H 0
#define SA_L (TILE_B)
#define SB_H (2*TILE_B)
#define STG  (3*TILE_B)  // 24576 per stage
#define NSTG 4
#define SMEM_GEMM (NSTG*STG) // 98304

__global__ __launch_bounds__(256, 1) void gemm_hmma_kernel(const float* __restrict__ bias)
{
    extern __shared__ char smem[];
    const uint32_t sbase = smem_u32(smem);
    const int tid = threadIdx.x;
    const int wid = tid >> 5, lane = tid & 31;
    const int n0 = blockIdx.x * BN;
    const int m0 = blockIdx.y * BM;
    const int stepi = blockIdx.z;
    const int wm = wid >> 2;     // 0..1
    const int wn = wid & 3;      // 0..3

    const __half* gAh = g_xh + (size_t)m0*CC;
    const __half* gAl = g_xl + (size_t)m0*CC;
    const __half* gB  = g_wh + ((size_t)stepi*CC + n0)*CC;

    const int lr0 = tid >> 2, lc = tid & 3;

    auto load_stage = [&](int kt, int s) {
        const int k0 = kt * BK;
        const uint32_t sa = sbase + s*STG;
        #pragma unroll
        for (int e = 0; e < 2; e++) {
            int r = lr0 + e*64;
            uint32_t so = sw_off(r, lc);
            size_t go = (size_t)r*CC + k0 + lc*8;
            cp_async16(sa + SA_H + so, gAh + go);
            cp_async16(sa + SA_L + so, gAl + go);
            cp_async16(sa + SB_H + so, gB + go);
        }
        cp_commit();
    };

    float acc[4][4][4];
    #pragma unroll
    for (int mt = 0; mt < 4; mt++)
        #pragma unroll
        for (int nt = 0; nt < 4; nt++)
            #pragma unroll
            for (int q = 0; q < 4; q++) acc[mt][nt][q] = 0.f;

    load_stage(0, 0);
    load_stage(1, 1);
    load_stage(2, 2);

    const int matid = lane >> 3, lrow = lane & 7;

    for (int kt = 0; kt < KITERS; kt++) {
        const int s = kt % NSTG;
        cp_wait2();
        __syncthreads();
        if (kt + 3 < KITERS) load_stage(kt + 3, (kt + 3) % NSTG);

        const uint32_t sa = sbase + s*STG;
        #pragma unroll
        for (int h = 0; h < 2; h++) {          // two k16 halves of BK=32
            const int cbase = h*2;
            uint32_t ah[4][4], al[4][4];
            #pragma unroll
            for (int mt = 0; mt < 4; mt++) {
                int m = wm*64 + mt*16 + ((matid & 1) ? 8 : 0) + lrow;
                int c = cbase + (matid >> 1);
                uint32_t so = sw_off(m, c);
                ldmx4(ah[mt], sa + SA_H + so);
                ldmx4(al[mt], sa + SA_L + so);
            }
            uint32_t bf[2][4];
            #pragma unroll
            for (int np = 0; np < 2; np++) {
                int n = wn*32 + np*16 + ((matid >> 1) ? 8 : 0) + lrow;
                int c = cbase + (matid & 1);
                uint32_t so = sw_off(n, c);
                ldmx4(bf[np], sa + SB_H + so);
            }
            #pragma unroll
            for (int mt = 0; mt < 4; mt++)
                #pragma unroll
                for (int nt = 0; nt < 4; nt++) {
                    const uint32_t* f = &bf[nt >> 1][(nt & 1)*2];
                    mma16816(acc[mt][nt], ah[mt], f);
                    mma16816(acc[mt][nt], al[mt], f);
                }
        }
    }

    // epilogue: write fp16 pairs
    const int mrow = wm*64 + (lane >> 2);
    const int ncol = wn*32 + (lane & 3)*2;
    #pragma unroll
    for (int nt = 0; nt < 4; nt++) {
        const int col = ncol + nt*8;
        const float b0 = bias[n0 + col], b1 = bias[n0 + col + 1];
        #pragma unroll
        for (int mt = 0; mt < 4; mt++) {
            __half* o = g_projh + ((size_t)stepi*BT + m0 + mrow + mt*16)*CC + n0 + col;
            *reinterpret_cast<__half2*>(o) =
                __floats2half2_rn(acc[mt][nt][0] + b0, acc[mt][nt][1] + b1);
            *reinterpret_cast<__half2*>(o + 8*CC) =
                __floats2half2_rn(acc[mt][nt][2] + b0, acc[mt][nt][3] + b1);
        }
    }
}

// ============================ logits dot kernel ============================
// One block per (b, t2): 11 fp32 targets + 12 fp16 proj rows in smem.
// 4 warps x 3 steps. smem = 11*768*4 + 12*768*2 = 52224 -> 4 CTAs/SM.
#define DOT_SMEM (11*CC*4 + 12*CC*2)

__global__ __launch_bounds__(128) void dot2_kernel(
    const int* __restrict__ neg, float* __restrict__ outp)
{
    extern __shared__ float ds[];
    float4* sT = reinterpret_cast<float4*>(ds);                    // [11][192] float4
    uint2*  sP = reinterpret_cast<uint2*>(ds + 11*CC);             // [12][192] uint2 (4 halves)
    const int b  = blockIdx.y;
    const int t2 = blockIdx.x + 1;        // 1..1023
    const int tid = threadIdx.x;
    const int nvalid = (t2 < STEPS) ? t2 : STEPS;

    const float4* yT4 = reinterpret_cast<const float4*>(g_yT);
    const uint2*  pj2 = reinterpret_cast<const uint2*>(g_projh);

    // load 11 target rows (fp32)
    for (int idx = tid; idx < 11*192; idx += 128) {
        int row = idx / 192, q = idx - row*192;
        int src = (row == 0) ? (b*TT + t2) : neg[b*(NNEG*TT) + (row-1)*TT + t2];
        sT[row*192 + q] = yT4[(size_t)src*192 + q];
    }
    // load valid proj rows (fp16; 192 uint2 per row)
    for (int idx = tid; idx < 12*192; idx += 128) {
        int i = idx / 192, q = idx - i*192;
        if (i < nvalid) {
            int t = t2 - 1 - i;
            sP[i*192 + q] = pj2[((size_t)i*BT + (size_t)b*TT + t)*192 + q];
        }
    }
    __syncthreads();

    const int wid = tid >> 5, lane = tid & 31;
    float acc[3][COPIES];
    #pragma unroll
    for (int j = 0; j < 3; j++)
        #pragma unroll
        for (int n = 0; n < COPIES; n++) acc[j][n] = 0.f;

    #pragma unroll
    for (int q = lane, it = 0; it < 192/32; q += 32, it++) {
        float4 tv[COPIES];
        #pragma unroll
        for (int n = 0; n < COPIES; n++) tv[n] = sT[n*192 + q];
        #pragma unroll
        for (int j = 0; j < 3; j++) {
            uint2 pw = sP[(wid*3 + j)*192 + q];
            float2 f0 = __half22float2(*reinterpret_cast<__half2*>(&pw.x));
            float2 f1 = __half22float2(*reinterpret_cast<__half2*>(&pw.y));
            #pragma unroll
            for (int n = 0; n < COPIES; n++)
                acc[j][n] += f0.x*tv[n].x + f0.y*tv[n].y + f1.x*tv[n].z + f1.y*tv[n].w;
        }
    }

    #pragma unroll
    for (int j = 0; j < 3; j++) {
        #pragma unroll
        for (int n = 0; n < COPIES; n++)
            #pragma unroll
            for (int s = 16; s > 0; s >>= 1)
                acc[j][n] += __shfl_xor_sync(0xffffffffu, acc[j][n], s);
        const int i = wid*3 + j;
        if (i < nvalid && lane == 0) {
            const int t = t2 - 1 - i;
            const int off = 16*(1023*i - (i*(i-1))/2);
            float* o = outp + (size_t)(off + t*BB + b)*COPIES;
            #pragma unroll
            for (int n = 0; n < COPIES; n++) o[n] = acc[j][n];
        }
    }
}

// ============================ host ============================
extern "C" void kernel_launch(void* const* d_in, const int* in_sizes, int n_in,
                              void* d_out, int out_size) {
    const float* x    = (const float*)d_in[0];
    const float* y    = (const float*)d_in[1];
    const float* W    = (const float*)d_in[2];
    const float* bias = (const float*)d_in[3];
    const int*   neg  = (const int*)d_in[4];
    float* out = (float*)d_out;

    int total_rows = 0;
    for (int i = 0; i < STEPS; i++) total_rows += (TT - 1 - i) * BB;  // 195360
    size_t npred = (size_t)total_rows * COPIES;

    if ((size_t)out_size > npred)
        cudaMemsetAsync((char*)d_out + npred * 4, 0, ((size_t)out_size - npred) * 4);

    static bool attr_set = false;
    if (!attr_set) {
        cudaFuncSetAttribute(gemm_hmma_kernel,
                             cudaFuncAttributeMaxDynamicSharedMemorySize, SMEM_GEMM);
        cudaFuncSetAttribute(dot2_kernel,
                             cudaFuncAttributeMaxDynamicSharedMemorySize, DOT_SMEM);
        attr_set = true;
    }

    {   // y transpose
        dim3 g(TT/32, CC/32, BB), blk(32, 8);
        transpose_y_kernel<<<g, blk>>>(y);
    }
    {   // x pack (fp16 hi/lo, transposed)
        dim3 g(TT/32, CC/32, BB), blk(32, 8);
        pack_x_kernel<<<g, blk>>>(x);
    }
    {   // W pack (fp16 single)
        size_t n = (size_t)STEPS*CC*CC;
        pack_w_kernel<<<(unsigned)((n + 255)/256), 256>>>(W);
    }
    {   // HMMA GEMM
        dim3 g(CC/BN, BT/BM, STEPS);   // (6, 128, 12)
        gemm_hmma_kernel<<<g, 256, SMEM_GEMM>>>(bias);
    }
    {   // logits
        dim3 g(TT-1, BB);              // (1023, 16)
        dot2_kernel<<<g, 128, DOT_SMEM>>>(neg, out);
    }
}

// round 9
// speedup vs baseline: 1.3621x; 1.0485x over previous
#include <cuda_runtime.h>
#include <cuda_fp16.h>
#include <cstdint>

#define BB 16
#define CC 768
#define TT 1024
#define STEPS 12
#define NNEG 10
#define COPIES 11
#define BT (BB*TT)  // 16384

// ---- scratch (static device globals; no runtime allocation) ----
__device__ __half g_yTh[(size_t)BB*TT*CC];        // [b][t][c] fp16
__device__ __half g_projh[(size_t)STEPS*BT*CC];   // [i][m][d] fp16
__device__ __half g_xh[(size_t)BT*CC];            // [m][c]
__device__ __half g_xl[(size_t)BT*CC];
__device__ __half g_wh[(size_t)STEPS*CC*CC];      // [(i*768+d)][c]

// ============================ asm helpers ============================
__device__ __forceinline__ uint32_t smem_u32(const void* p) {
    uint32_t a;
    asm("{ .reg .u64 t; cvta.to.shared.u64 t, %1; cvt.u32.u64 %0, t; }" : "=r"(a) : "l"(p));
    return a;
}

__device__ __forceinline__ void cp_async16(uint32_t saddr, const void* gaddr) {
    asm volatile("cp.async.cg.shared.global [%0], [%1], 16;" :: "r"(saddr), "l"(gaddr));
}
__device__ __forceinline__ void cp_commit() {
    asm volatile("cp.async.commit_group;" ::: "memory");
}
__device__ __forceinline__ void cp_wait2() {
    asm volatile("cp.async.wait_group 2;" ::: "memory");
}

__device__ __forceinline__ void ldmx4(uint32_t* r, uint32_t addr) {
    asm volatile("ldmatrix.sync.aligned.m8n8.x4.shared.b16 {%0,%1,%2,%3}, [%4];"
        : "=r"(r[0]), "=r"(r[1]), "=r"(r[2]), "=r"(r[3]) : "r"(addr));
}

__device__ __forceinline__ void mma16816(float* d, const uint32_t* a, const uint32_t* b) {
    asm volatile("mma.sync.aligned.m16n8k16.row.col.f32.f16.f16.f32 "
        "{%0,%1,%2,%3}, {%4,%5,%6,%7}, {%8,%9}, {%0,%1,%2,%3};"
        : "+f"(d[0]), "+f"(d[1]), "+f"(d[2]), "+f"(d[3])
        : "r"(a[0]), "r"(a[1]), "r"(a[2]), "r"(a[3]), "r"(b[0]), "r"(b[1]));
}

// swizzled byte offset for a (row, 16B-chunk) of a [rows][32] fp16 tile
__device__ __forceinline__ uint32_t sw_off(int r, int c) {
    uint32_t bo = r*64 + c*16;
    return bo ^ (((bo >> 7) & 7) << 4);
}

// ============================ prepack kernels ============================
__global__ void transpose_y_kernel(const float* __restrict__ y) {
    __shared__ float tile[32][33];
    int b = blockIdx.z, c0 = blockIdx.y * 32, t0 = blockIdx.x * 32;
    int tx = threadIdx.x, ty = threadIdx.y;
    #pragma unroll
    for (int j = 0; j < 32; j += 8)
        tile[ty + j][tx] = y[((size_t)b*CC + c0 + ty + j)*TT + t0 + tx];
    __syncthreads();
    #pragma unroll
    for (int j = 0; j < 32; j += 8)
        g_yTh[((size_t)b*TT + t0 + ty + j)*CC + c0 + tx] =
            __float2half_rn(tile[tx][ty + j]);
}

__global__ void pack_x_kernel(const float* __restrict__ x) {
    __shared__ float tile[32][33];
    int b = blockIdx.z, c0 = blockIdx.y * 32, t0 = blockIdx.x * 32;
    int tx = threadIdx.x, ty = threadIdx.y;
    #pragma unroll
    for (int j = 0; j < 32; j += 8)
        tile[ty + j][tx] = x[((size_t)b*CC + c0 + ty + j)*TT + t0 + tx];
    __syncthreads();
    #pragma unroll
    for (int j = 0; j < 32; j += 8) {
        float v = tile[tx][ty + j];
        __half h = __float2half_rn(v);
        __half l = __float2half_rn(v - __half2float(h));
        size_t o = ((size_t)b*TT + t0 + ty + j)*CC + c0 + tx;
        g_xh[o] = h;
        g_xl[o] = l;
    }
}

__global__ void pack_w_kernel(const float* __restrict__ W) {
    size_t o = (size_t)blockIdx.x * blockDim.x + threadIdx.x;
    if (o >= (size_t)STEPS*CC*CC) return;
    int c = (int)(o % CC);
    int d = (int)((o / CC) % CC);
    int i = (int)(o / ((size_t)CC*CC));
    g_wh[o] = __float2half_rn(W[((size_t)c*CC + d)*STEPS + i]);
}

// ============================ HMMA GEMM ============================
// fp16 2-pass: proj = xh*w + xl*w (+bias), output fp16.
// Tile 128x128x32, 256 thr (2x4 warps, warp=64x32), 4-stage cp.async.
// MMA issue order: full hi-pass then full lo-pass (no back-to-back RAW on acc).
#define BM 128
#define BN 128
#define BK 32
#define KITERS (CC/BK)   // 24
#define TILE_B (BM*BK*2) // 8192 bytes per sub-tile
#define SA_H 0
#define SA_L (TILE_B)
#define SB_H (2*TILE_B)
#define STG  (3*TILE_B)  // 24576 per stage
#define NSTG 4
#define SMEM_GEMM (NSTG*STG) // 98304

__global__ __launch_bounds__(256, 1) void gemm_hmma_kernel(const float* __restrict__ bias)
{
    extern __shared__ char smem[];
    const uint32_t sbase = smem_u32(smem);
    const int tid = threadIdx.x;
    const int wid = tid >> 5, lane = tid & 31;
    const int n0 = blockIdx.x * BN;
    const int m0 = blockIdx.y * BM;
    const int stepi = blockIdx.z;
    const int wm = wid >> 2;     // 0..1
    const int wn = wid & 3;      // 0..3

    const __half* gAh = g_xh + (size_t)m0*CC;
    const __half* gAl = g_xl + (size_t)m0*CC;
    const __half* gB  = g_wh + ((size_t)stepi*CC + n0)*CC;

    const int lr0 = tid >> 2, lc = tid & 3;

    auto load_stage = [&](int kt, int s) {
        const int k0 = kt * BK;
        const uint32_t sa = sbase + s*STG;
        #pragma unroll
        for (int e = 0; e < 2; e++) {
            int r = lr0 + e*64;
            uint32_t so = sw_off(r, lc);
            size_t go = (size_t)r*CC + k0 + lc*8;
            cp_async16(sa + SA_H + so, gAh + go);
            cp_async16(sa + SA_L + so, gAl + go);
            cp_async16(sa + SB_H + so, gB + go);
        }
        cp_commit();
    };

    float acc[4][4][4];
    #pragma unroll
    for (int mt = 0; mt < 4; mt++)
        #pragma unroll
        for (int nt = 0; nt < 4; nt++)
            #pragma unroll
            for (int q = 0; q < 4; q++) acc[mt][nt][q] = 0.f;

    load_stage(0, 0);
    load_stage(1, 1);
    load_stage(2, 2);

    const int matid = lane >> 3, lrow = lane & 7;

    for (int kt = 0; kt < KITERS; kt++) {
        const int s = kt % NSTG;
        cp_wait2();
        __syncthreads();
        if (kt + 3 < KITERS) load_stage(kt + 3, (kt + 3) % NSTG);

        const uint32_t sa = sbase + s*STG;
        #pragma unroll
        for (int h = 0; h < 2; h++) {          // two k16 halves of BK=32
            const int cbase = h*2;
            uint32_t ah[4][4], al[4][4];
            #pragma unroll
            for (int mt = 0; mt < 4; mt++) {
                int m = wm*64 + mt*16 + ((matid & 1) ? 8 : 0) + lrow;
                int c = cbase + (matid >> 1);
                uint32_t so = sw_off(m, c);
                ldmx4(ah[mt], sa + SA_H + so);
                ldmx4(al[mt], sa + SA_L + so);
            }
            uint32_t bf[2][4];
            #pragma unroll
            for (int np = 0; np < 2; np++) {
                int n = wn*32 + np*16 + ((matid >> 1) ? 8 : 0) + lrow;
                int c = cbase + (matid & 1);
                uint32_t so = sw_off(n, c);
                ldmx4(bf[np], sa + SB_H + so);
            }
            // hi pass: 16 independent MMAs
            #pragma unroll
            for (int mt = 0; mt < 4; mt++)
                #pragma unroll
                for (int nt = 0; nt < 4; nt++)
                    mma16816(acc[mt][nt], ah[mt], &bf[nt >> 1][(nt & 1)*2]);
            // lo pass: 16 independent MMAs (each 16 issues after its RAW producer)
            #pragma unroll
            for (int mt = 0; mt < 4; mt++)
                #pragma unroll
                for (int nt = 0; nt < 4; nt++)
                    mma16816(acc[mt][nt], al[mt], &bf[nt >> 1][(nt & 1)*2]);
        }
    }

    // epilogue: write fp16 pairs
    const int mrow = wm*64 + (lane >> 2);
    const int ncol = wn*32 + (lane & 3)*2;
    #pragma unroll
    for (int nt = 0; nt < 4; nt++) {
        const int col = ncol + nt*8;
        const float b0 = bias[n0 + col], b1 = bias[n0 + col + 1];
        #pragma unroll
        for (int mt = 0; mt < 4; mt++) {
            __half* o = g_projh + ((size_t)stepi*BT + m0 + mrow + mt*16)*CC + n0 + col;
            *reinterpret_cast<__half2*>(o) =
                __floats2half2_rn(acc[mt][nt][0] + b0, acc[mt][nt][1] + b1);
            *reinterpret_cast<__half2*>(o + 8*CC) =
                __floats2half2_rn(acc[mt][nt][2] + b0, acc[mt][nt][3] + b1);
        }
    }
}

// ============================ logits dot kernel ============================
// One block per (b, t2): 11 fp16 targets + 12 fp16 proj rows in smem (34.5KB).
// 4 warps x 3 steps.
#define DOT_SMEM (23*CC*2)   // 35328

__global__ __launch_bounds__(128) void dot2_kernel(
    const int* __restrict__ neg, float* __restrict__ outp)
{
    extern __shared__ char dsm[];
    uint2* sT = reinterpret_cast<uint2*>(dsm);                 // [11][192] (4 halves each)
    uint2* sP = reinterpret_cast<uint2*>(dsm + 11*CC*2);       // [12][192]
    const int b  = blockIdx.y;
    const int t2 = blockIdx.x + 1;        // 1..1023
    const int tid = threadIdx.x;
    const int nvalid = (t2 < STEPS) ? t2 : STEPS;

    const uint2* yT2 = reinterpret_cast<const uint2*>(g_yTh);
    const uint2* pj2 = reinterpret_cast<const uint2*>(g_projh);

    // load 11 target rows (fp16)
    for (int idx = tid; idx < 11*192; idx += 128) {
        int row = idx / 192, q = idx - row*192;
        int src = (row == 0) ? (b*TT + t2) : neg[b*(NNEG*TT) + (row-1)*TT + t2];
        sT[row*192 + q] = yT2[(size_t)src*192 + q];
    }
    // load valid proj rows (fp16)
    for (int idx = tid; idx < 12*192; idx += 128) {
        int i = idx / 192, q = idx - i*192;
        if (i < nvalid) {
            int t = t2 - 1 - i;
            sP[i*192 + q] = pj2[((size_t)i*BT + (size_t)b*TT + t)*192 + q];
        }
    }
    __syncthreads();

    const int wid = tid >> 5, lane = tid & 31;
    float acc[3][COPIES];
    #pragma unroll
    for (int j = 0; j < 3; j++)
        #pragma unroll
        for (int n = 0; n < COPIES; n++) acc[j][n] = 0.f;

    #pragma unroll
    for (int q = lane, it = 0; it < 192/32; q += 32, it++) {
        float4 tv[COPIES];
        #pragma unroll
        for (int n = 0; n < COPIES; n++) {
            uint2 tw = sT[n*192 + q];
            float2 t0 = __half22float2(*reinterpret_cast<__half2*>(&tw.x));
            float2 t1 = __half22float2(*reinterpret_cast<__half2*>(&tw.y));
            tv[n] = make_float4(t0.x, t0.y, t1.x, t1.y);
        }
        #pragma unroll
        for (int j = 0; j < 3; j++) {
            uint2 pw = sP[(wid*3 + j)*192 + q];
            float2 f0 = __half22float2(*reinterpret_cast<__half2*>(&pw.x));
            float2 f1 = __half22float2(*reinterpret_cast<__half2*>(&pw.y));
            #pragma unroll
            for (int n = 0; n < COPIES; n++)
                acc[j][n] += f0.x*tv[n].x + f0.y*tv[n].y + f1.x*tv[n].z + f1.y*tv[n].w;
        }
    }

    #pragma unroll
    for (int j = 0; j < 3; j++) {
        #pragma unroll
        for (int n = 0; n < COPIES; n++)
            #pragma unroll
            for (int s = 16; s > 0; s >>= 1)
                acc[j][n] += __shfl_xor_sync(0xffffffffu, acc[j][n], s);
        const int i = wid*3 + j;
        if (i < nvalid && lane == 0) {
            const int t = t2 - 1 - i;
            const int off = 16*(1023*i - (i*(i-1))/2);
            float* o = outp + (size_t)(off + t*BB + b)*COPIES;
            #pragma unroll
            for (int n = 0; n < COPIES; n++) o[n] = acc[j][n];
        }
    }
}

// ============================ host ============================
extern "C" void kernel_launch(void* const* d_in, const int* in_sizes, int n_in,
                              void* d_out, int out_size) {
    const float* x    = (const float*)d_in[0];
    const float* y    = (const float*)d_in[1];
    const float* W    = (const float*)d_in[2];
    const float* bias = (const float*)d_in[3];
    const int*   neg  = (const int*)d_in[4];
    float* out = (float*)d_out;

    int total_rows = 0;
    for (int i = 0; i < STEPS; i++) total_rows += (TT - 1 - i) * BB;  // 195360
    size_t npred = (size_t)total_rows * COPIES;

    if ((size_t)out_size > npred)
        cudaMemsetAsync((char*)d_out + npred * 4, 0, ((size_t)out_size - npred) * 4);

    static bool attr_set = false;
    if (!attr_set) {
        cudaFuncSetAttribute(gemm_hmma_kernel,
                             cudaFuncAttributeMaxDynamicSharedMemorySize, SMEM_GEMM);
        cudaFuncSetAttribute(dot2_kernel,
                             cudaFuncAttributeMaxDynamicSharedMemorySize, DOT_SMEM);
        attr_set = true;
    }

    {   // y transpose -> fp16
        dim3 g(TT/32, CC/32, BB), blk(32, 8);
        transpose_y_kernel<<<g, blk>>>(y);
    }
    {   // x pack (fp16 hi/lo, transposed)
        dim3 g(TT/32, CC/32, BB), blk(32, 8);
        pack_x_kernel<<<g, blk>>>(x);
    }
    {   // W pack (fp16 single)
        size_t n = (size_t)STEPS*CC*CC;
        pack_w_kernel<<<(unsigned)((n + 255)/256), 256>>>(W);
    }
    {   // HMMA GEMM
        dim3 g(CC/BN, BT/BM, STEPS);   // (6, 128, 12)
        gemm_hmma_kernel<<<g, 256, SMEM_GEMM>>>(bias);
    }
    {   // logits
        dim3 g(TT-1, BB);              // (1023, 16)
        dot2_kernel<<<g, 128, DOT_SMEM>>>(neg, out);
    }
}

// round 10
// speedup vs baseline: 2.2273x; 1.6352x over previous
#include <cuda_runtime.h>
#include <cuda_fp16.h>
#include <cstdint>

#define BB 16
#define CC 768
#define TT 1024
#define STEPS 12
#define NNEG 10
#define COPIES 11
#define BT (BB*TT)  // 16384

// ---- scratch (static device globals; no runtime allocation) ----
__device__ __half g_yTh[(size_t)BB*TT*CC];        // [b][t][c] fp16
__device__ __half g_projh[(size_t)STEPS*BT*CC];   // [i][m][d] fp16
__device__ __half g_xh[(size_t)BT*CC];            // [m][c] fp16
__device__ __half g_wh[(size_t)STEPS*CC*CC];      // [(i*768+d)][c] fp16

// ============================ asm helpers ============================
__device__ __forceinline__ uint32_t smem_u32(const void* p) {
    uint32_t a;
    asm("{ .reg .u64 t; cvta.to.shared.u64 t, %1; cvt.u32.u64 %0, t; }" : "=r"(a) : "l"(p));
    return a;
}

__device__ __forceinline__ void cp_async16(uint32_t saddr, const void* gaddr) {
    asm volatile("cp.async.cg.shared.global [%0], [%1], 16;" :: "r"(saddr), "l"(gaddr));
}
__device__ __forceinline__ void cp_commit() {
    asm volatile("cp.async.commit_group;" ::: "memory");
}
__device__ __forceinline__ void cp_wait2() {
    asm volatile("cp.async.wait_group 2;" ::: "memory");
}

__device__ __forceinline__ void ldmx4(uint32_t* r, uint32_t addr) {
    asm volatile("ldmatrix.sync.aligned.m8n8.x4.shared.b16 {%0,%1,%2,%3}, [%4];"
        : "=r"(r[0]), "=r"(r[1]), "=r"(r[2]), "=r"(r[3]) : "r"(addr));
}

__device__ __forceinline__ void mma16816(float* d, const uint32_t* a, const uint32_t* b) {
    asm volatile("mma.sync.aligned.m16n8k16.row.col.f32.f16.f16.f32 "
        "{%0,%1,%2,%3}, {%4,%5,%6,%7}, {%8,%9}, {%0,%1,%2,%3};"
        : "+f"(d[0]), "+f"(d[1]), "+f"(d[2]), "+f"(d[3])
        : "r"(a[0]), "r"(a[1]), "r"(a[2]), "r"(a[3]), "r"(b[0]), "r"(b[1]));
}

// swizzled byte offset for a (row, 16B-chunk) of a [rows][32] fp16 tile
__device__ __forceinline__ uint32_t sw_off(int r, int c) {
    uint32_t bo = r*64 + c*16;
    return bo ^ (((bo >> 7) & 7) << 4);
}

// ============================ prepack kernels ============================
__global__ void transpose_y_kernel(const float* __restrict__ y) {
    __shared__ float tile[32][33];
    int b = blockIdx.z, c0 = blockIdx.y * 32, t0 = blockIdx.x * 32;
    int tx = threadIdx.x, ty = threadIdx.y;
    #pragma unroll
    for (int j = 0; j < 32; j += 8)
        tile[ty + j][tx] = y[((size_t)b*CC + c0 + ty + j)*TT + t0 + tx];
    __syncthreads();
    #pragma unroll
    for (int j = 0; j < 32; j += 8)
        g_yTh[((size_t)b*TT + t0 + ty + j)*CC + c0 + tx] =
            __float2half_rn(tile[tx][ty + j]);
}

__global__ void pack_x_kernel(const float* __restrict__ x) {
    __shared__ float tile[32][33];
    int b = blockIdx.z, c0 = blockIdx.y * 32, t0 = blockIdx.x * 32;
    int tx = threadIdx.x, ty = threadIdx.y;
    #pragma unroll
    for (int j = 0; j < 32; j += 8)
        tile[ty + j][tx] = x[((size_t)b*CC + c0 + ty + j)*TT + t0 + tx];
    __syncthreads();
    #pragma unroll
    for (int j = 0; j < 32; j += 8)
        g_xh[((size_t)b*TT + t0 + ty + j)*CC + c0 + tx] =
            __float2half_rn(tile[tx][ty + j]);
}

__global__ void pack_w_kernel(const float* __restrict__ W) {
    size_t o = (size_t)blockIdx.x * blockDim.x + threadIdx.x;
    if (o >= (size_t)STEPS*CC*CC) return;
    int c = (int)(o % CC);
    int d = (int)((o / CC) % CC);
    int i = (int)(o / ((size_t)CC*CC));
    g_wh[o] = __float2half_rn(W[((size_t)c*CC + d)*STEPS + i]);
}

// ============================ HMMA GEMM ============================
// Single-pass fp16: proj = x*w (+bias), output fp16.
// Tile 128x128x32, 256 thr (2x4 warps, warp=64x32), 4-stage cp.async,
// 16KB/stage -> 64KB smem, 2 CTAs/SM.
#define BM 128
#define BN 128
#define BK 32
#define KITERS (CC/BK)   // 24
#define TILE_B (BM*BK*2) // 8192 bytes per sub-tile
#define SA_H 0
#define SB_H (TILE_B)
#define STG  (2*TILE_B)  // 16384 per stage
#define NSTG 4
#define SMEM_GEMM (NSTG*STG) // 65536

__global__ __launch_bounds__(256, 2) void gemm_hmma_kernel(const float* __restrict__ bias)
{
    extern __shared__ char smem[];
    const uint32_t sbase = smem_u32(smem);
    const int tid = threadIdx.x;
    const int wid = tid >> 5, lane = tid & 31;
    const int n0 = blockIdx.x * BN;
    const int m0 = blockIdx.y * BM;
    const int stepi = blockIdx.z;
    const int wm = wid >> 2;     // 0..1
    const int wn = wid & 3;      // 0..3

    const __half* gA = g_xh + (size_t)m0*CC;
    const __half* gB = g_wh + ((size_t)stepi*CC + n0)*CC;

    const int lr0 = tid >> 2, lc = tid & 3;

    auto load_stage = [&](int kt, int s) {
        const int k0 = kt * BK;
        const uint32_t sa = sbase + s*STG;
        #pragma unroll
        for (int e = 0; e < 2; e++) {
            int r = lr0 + e*64;
            uint32_t so = sw_off(r, lc);
            size_t go = (size_t)r*CC + k0 + lc*8;
            cp_async16(sa + SA_H + so, gA + go);
            cp_async16(sa + SB_H + so, gB + go);
        }
        cp_commit();
    };

    float acc[4][4][4];
    #pragma unroll
    for (int mt = 0; mt < 4; mt++)
        #pragma unroll
        for (int nt = 0; nt < 4; nt++)
            #pragma unroll
            for (int q = 0; q < 4; q++) acc[mt][nt][q] = 0.f;

    load_stage(0, 0);
    load_stage(1, 1);
    load_stage(2, 2);

    const int matid = lane >> 3, lrow = lane & 7;

    for (int kt = 0; kt < KITERS; kt++) {
        const int s = kt % NSTG;
        cp_wait2();
        __syncthreads();
        if (kt + 3 < KITERS) load_stage(kt + 3, (kt + 3) % NSTG);

        const uint32_t sa = sbase + s*STG;
        #pragma unroll
        for (int h = 0; h < 2; h++) {          // two k16 halves of BK=32
            const int cbase = h*2;
            uint32_t ah[4][4];
            #pragma unroll
            for (int mt = 0; mt < 4; mt++) {
                int m = wm*64 + mt*16 + ((matid & 1) ? 8 : 0) + lrow;
                int c = cbase + (matid >> 1);
                ldmx4(ah[mt], sa + SA_H + sw_off(m, c));
            }
            uint32_t bf[2][4];
            #pragma unroll
            for (int np = 0; np < 2; np++) {
                int n = wn*32 + np*16 + ((matid >> 1) ? 8 : 0) + lrow;
                int c = cbase + (matid & 1);
                ldmx4(bf[np], sa + SB_H + sw_off(n, c));
            }
            #pragma unroll
            for (int mt = 0; mt < 4; mt++)
                #pragma unroll
                for (int nt = 0; nt < 4; nt++)
                    mma16816(acc[mt][nt], ah[mt], &bf[nt >> 1][(nt & 1)*2]);
        }
    }

    // epilogue: write fp16 pairs
    const int mrow = wm*64 + (lane >> 2);
    const int ncol = wn*32 + (lane & 3)*2;
    #pragma unroll
    for (int nt = 0; nt < 4; nt++) {
        const int col = ncol + nt*8;
        const float b0 = bias[n0 + col], b1 = bias[n0 + col + 1];
        #pragma unroll
        for (int mt = 0; mt < 4; mt++) {
            __half* o = g_projh + ((size_t)stepi*BT + m0 + mrow + mt*16)*CC + n0 + col;
            *reinterpret_cast<__half2*>(o) =
                __floats2half2_rn(acc[mt][nt][0] + b0, acc[mt][nt][1] + b1);
            *reinterpret_cast<__half2*>(o + 8*CC) =
                __floats2half2_rn(acc[mt][nt][2] + b0, acc[mt][nt][3] + b1);
        }
    }
}

// ============================ logits dot kernel ============================
// One block per (b, t2): 11 fp16 targets + 12 fp16 proj rows in smem (34.5KB).
// 4 warps x 3 steps.
#define DOT_SMEM (23*CC*2)   // 35328

__global__ __launch_bounds__(128) void dot2_kernel(
    const int* __restrict__ neg, float* __restrict__ outp)
{
    extern __shared__ char dsm[];
    uint2* sT = reinterpret_cast<uint2*>(dsm);                 // [11][192] (4 halves each)
    uint2* sP = reinterpret_cast<uint2*>(dsm + 11*CC*2);       // [12][192]
    const int b  = blockIdx.y;
    const int t2 = blockIdx.x + 1;        // 1..1023
    const int tid = threadIdx.x;
    const int nvalid = (t2 < STEPS) ? t2 : STEPS;

    const uint2* yT2 = reinterpret_cast<const uint2*>(g_yTh);
    const uint2* pj2 = reinterpret_cast<const uint2*>(g_projh);

    for (int idx = tid; idx < 11*192; idx += 128) {
        int row = idx / 192, q = idx - row*192;
        int src = (row == 0) ? (b*TT + t2) : neg[b*(NNEG*TT) + (row-1)*TT + t2];
        sT[row*192 + q] = yT2[(size_t)src*192 + q];
    }
    for (int idx = tid; idx < 12*192; idx += 128) {
        int i = idx / 192, q = idx - i*192;
        if (i < nvalid) {
            int t = t2 - 1 - i;
            sP[i*192 + q] = pj2[((size_t)i*BT + (size_t)b*TT + t)*192 + q];
        }
    }
    __syncthreads();

    const int wid = tid >> 5, lane = tid & 31;
    float acc[3][COPIES];
    #pragma unroll
    for (int j = 0; j < 3; j++)
        #pragma unroll
        for (int n = 0; n < COPIES; n++) acc[j][n] = 0.f;

    #pragma unroll
    for (int q = lane, it = 0; it < 192/32; q += 32, it++) {
        float4 tv[COPIES];
        #pragma unroll
        for (int n = 0; n < COPIES; n++) {
            uint2 tw = sT[n*192 + q];
            float2 t0 = __half22float2(*reinterpret_cast<__half2*>(&tw.x));
            float2 t1 = __half22float2(*reinterpret_cast<__half2*>(&tw.y));
            tv[n] = make_float4(t0.x, t0.y, t1.x, t1.y);
        }
        #pragma unroll
        for (int j = 0; j < 3; j++) {
            uint2 pw = sP[(wid*3 + j)*192 + q];
            float2 f0 = __half22float2(*reinterpret_cast<__half2*>(&pw.x));
            float2 f1 = __half22float2(*reinterpret_cast<__half2*>(&pw.y));
            #pragma unroll
            for (int n = 0; n < COPIES; n++)
                acc[j][n] += f0.x*tv[n].x + f0.y*tv[n].y + f1.x*tv[n].z + f1.y*tv[n].w;
        }
    }

    #pragma unroll
    for (int j = 0; j < 3; j++) {
        #pragma unroll
        for (int n = 0; n < COPIES; n++)
            #pragma unroll
            for (int s = 16; s > 0; s >>= 1)
                acc[j][n] += __shfl_xor_sync(0xffffffffu, acc[j][n], s);
        const int i = wid*3 + j;
        if (i < nvalid && lane == 0) {
            const int t = t2 - 1 - i;
            const int off = 16*(1023*i - (i*(i-1))/2);
            float* o = outp + (size_t)(off + t*BB + b)*COPIES;
            #pragma unroll
            for (int n = 0; n < COPIES; n++) o[n] = acc[j][n];
        }
    }
}

// ============================ host ============================
extern "C" void kernel_launch(void* const* d_in, const int* in_sizes, int n_in,
                              void* d_out, int out_size) {
    const float* x    = (const float*)d_in[0];
    const float* y    = (const float*)d_in[1];
    const float* W    = (const float*)d_in[2];
    const float* bias = (const float*)d_in[3];
    const int*   neg  = (const int*)d_in[4];
    float* out = (float*)d_out;

    int total_rows = 0;
    for (int i = 0; i < STEPS; i++) total_rows += (TT - 1 - i) * BB;  // 195360
    size_t npred = (size_t)total_rows * COPIES;

    if ((size_t)out_size > npred)
        cudaMemsetAsync((char*)d_out + npred * 4, 0, ((size_t)out_size - npred) * 4);

    static bool attr_set = false;
    if (!attr_set) {
        cudaFuncSetAttribute(gemm_hmma_kernel,
                             cudaFuncAttributeMaxDynamicSharedMemorySize, SMEM_GEMM);
        cudaFuncSetAttribute(dot2_kernel,
                             cudaFuncAttributeMaxDynamicSharedMemorySize, DOT_SMEM);
        attr_set = true;
    }

    {   // y transpose -> fp16
        dim3 g(TT/32, CC/32, BB), blk(32, 8);
        transpose_y_kernel<<<g, blk>>>(y);
    }
    {   // x pack (fp16, transposed)
        dim3 g(TT/32, CC/32, BB), blk(32, 8);
        pack_x_kernel<<<g, blk>>>(x);
    }
    {   // W pack (fp16)
        size_t n = (size_t)STEPS*CC*CC;
        pack_w_kernel<<<(unsigned)((n + 255)/256), 256>>>(W);
    }
    {   // HMMA GEMM
        dim3 g(CC/BN, BT/BM, STEPS);   // (6, 128, 12)
        gemm_hmma_kernel<<<g, 256, SMEM_GEMM>>>(bias);
    }
    {   // logits
        dim3 g(TT-1, BB);              // (1023, 16)
        dot2_kernel<<<g, 128, DOT_SMEM>>>(neg, out);
    }
}

// round 11
// speedup vs baseline: 2.3028x; 1.0339x over previous
#include <cuda_runtime.h>
#include <cuda_fp16.h>
#include <cstdint>

#define BB 16
#define CC 768
#define TT 1024
#define STEPS 12
#define NNEG 10
#define COPIES 11
#define BT (BB*TT)  // 16384

// ---- scratch (static device globals; no runtime allocation) ----
__device__ __half g_yTh[(size_t)BB*TT*CC];        // [b][t][c] fp16
__device__ __half g_projh[(size_t)STEPS*BT*CC];   // [i][m][d] fp16
__device__ __half g_xh[(size_t)BT*CC];            // [m][c] fp16
__device__ __half g_wh[(size_t)STEPS*CC*CC];      // [(i*768+d)][c] fp16

// ============================ asm helpers ============================
__device__ __forceinline__ uint32_t smem_u32(const void* p) {
    uint32_t a;
    asm("{ .reg .u64 t; cvta.to.shared.u64 t, %1; cvt.u32.u64 %0, t; }" : "=r"(a) : "l"(p));
    return a;
}

__device__ __forceinline__ void cp_async16(uint32_t saddr, const void* gaddr) {
    asm volatile("cp.async.cg.shared.global [%0], [%1], 16;" :: "r"(saddr), "l"(gaddr));
}
__device__ __forceinline__ void cp_commit() {
    asm volatile("cp.async.commit_group;" ::: "memory");
}
__device__ __forceinline__ void cp_wait2() {
    asm volatile("cp.async.wait_group 2;" ::: "memory");
}

__device__ __forceinline__ void ldmx4(uint32_t* r, uint32_t addr) {
    asm volatile("ldmatrix.sync.aligned.m8n8.x4.shared.b16 {%0,%1,%2,%3}, [%4];"
        : "=r"(r[0]), "=r"(r[1]), "=r"(r[2]), "=r"(r[3]) : "r"(addr));
}

__device__ __forceinline__ void mma16816(float* d, const uint32_t* a, const uint32_t* b) {
    asm volatile("mma.sync.aligned.m16n8k16.row.col.f32.f16.f16.f32 "
        "{%0,%1,%2,%3}, {%4,%5,%6,%7}, {%8,%9}, {%0,%1,%2,%3};"
        : "+f"(d[0]), "+f"(d[1]), "+f"(d[2]), "+f"(d[3])
        : "r"(a[0]), "r"(a[1]), "r"(a[2]), "r"(a[3]), "r"(b[0]), "r"(b[1]));
}

// swizzled byte offset for a (row, 16B-chunk) of a [rows][32] fp16 tile
__device__ __forceinline__ uint32_t sw_off(int r, int c) {
    uint32_t bo = r*64 + c*16;
    return bo ^ (((bo >> 7) & 7) << 4);
}

// ============================ prepack kernels ============================
// fused x+y transpose -> fp16 [b][t][c]
__global__ void pack_xy_kernel(const float* __restrict__ x, const float* __restrict__ y) {
    __shared__ float tx_[32][33];
    __shared__ float ty_[32][33];
    int b = blockIdx.z, c0 = blockIdx.y * 32, t0 = blockIdx.x * 32;
    int tx = threadIdx.x, ty = threadIdx.y;
    #pragma unroll
    for (int j = 0; j < 32; j += 8) {
        size_t src = ((size_t)b*CC + c0 + ty + j)*TT + t0 + tx;
        tx_[ty + j][tx] = x[src];
        ty_[ty + j][tx] = y[src];
    }
    __syncthreads();
    #pragma unroll
    for (int j = 0; j < 32; j += 8) {
        size_t dst = ((size_t)b*TT + t0 + ty + j)*CC + c0 + tx;
        g_xh[dst]  = __float2half_rn(tx_[tx][ty + j]);
        g_yTh[dst] = __float2half_rn(ty_[tx][ty + j]);
    }
}

// W[c][d][i] -> g_wh[(i*768+d)][c], coalesced reads (i-contiguous float4s)
// and coalesced writes (c-contiguous halves) via padded smem transpose.
__global__ void pack_w_kernel(const float* __restrict__ W) {
    __shared__ __half sw[32][33][STEPS];
    const int c0 = blockIdx.x * 32, d0 = blockIdx.y * 32;
    const int tx = threadIdx.x, ty = threadIdx.y;
    #pragma unroll
    for (int j = 0; j < 4; j++) {
        int cl = ty + j*8;
        const float4* src = reinterpret_cast<const float4*>(
            W + ((size_t)(c0 + cl)*CC + d0 + tx)*STEPS);
        float4 a = src[0], bq = src[1], cq = src[2];
        __half* o = &sw[cl][tx][0];
        o[0] = __float2half_rn(a.x);  o[1] = __float2half_rn(a.y);
        o[2] = __float2half_rn(a.z);  o[3] = __float2half_rn(a.w);
        o[4] = __float2half_rn(bq.x); o[5] = __float2half_rn(bq.y);
        o[6] = __float2half_rn(bq.z); o[7] = __float2half_rn(bq.w);
        o[8] = __float2half_rn(cq.x); o[9] = __float2half_rn(cq.y);
        o[10] = __float2half_rn(cq.z); o[11] = __float2half_rn(cq.w);
    }
    __syncthreads();
    #pragma unroll
    for (int i = 0; i < STEPS; i++)
        #pragma unroll
        for (int j = 0; j < 4; j++) {
            int dl = ty + j*8;
            g_wh[((size_t)i*CC + d0 + dl)*CC + c0 + tx] = sw[tx][dl][i];
        }
}

// ============================ HMMA GEMM ============================
// Single-pass fp16: proj = x*w (+bias), output fp16.  (unchanged, proven)
#define BM 128
#define BN 128
#define BK 32
#define KITERS (CC/BK)   // 24
#define TILE_B (BM*BK*2) // 8192 bytes per sub-tile
#define SA_H 0
#define SB_H (TILE_B)
#define STG  (2*TILE_B)  // 16384 per stage
#define NSTG 4
#define SMEM_GEMM (NSTG*STG) // 65536

__global__ __launch_bounds__(256, 2) void gemm_hmma_kernel(const float* __restrict__ bias)
{
    extern __shared__ char smem[];
    const uint32_t sbase = smem_u32(smem);
    const int tid = threadIdx.x;
    const int wid = tid >> 5, lane = tid & 31;
    const int n0 = blockIdx.x * BN;
    const int m0 = blockIdx.y * BM;
    const int stepi = blockIdx.z;
    const int wm = wid >> 2;     // 0..1
    const int wn = wid & 3;      // 0..3

    const __half* gA = g_xh + (size_t)m0*CC;
    const __half* gB = g_wh + ((size_t)stepi*CC + n0)*CC;

    const int lr0 = tid >> 2, lc = tid & 3;

    auto load_stage = [&](int kt, int s) {
        const int k0 = kt * BK;
        const uint32_t sa = sbase + s*STG;
        #pragma unroll
        for (int e = 0; e < 2; e++) {
            int r = lr0 + e*64;
            uint32_t so = sw_off(r, lc);
            size_t go = (size_t)r*CC + k0 + lc*8;
            cp_async16(sa + SA_H + so, gA + go);
            cp_async16(sa + SB_H + so, gB + go);
        }
        cp_commit();
    };

    float acc[4][4][4];
    #pragma unroll
    for (int mt = 0; mt < 4; mt++)
        #pragma unroll
        for (int nt = 0; nt < 4; nt++)
            #pragma unroll
            for (int q = 0; q < 4; q++) acc[mt][nt][q] = 0.f;

    load_stage(0, 0);
    load_stage(1, 1);
    load_stage(2, 2);

    const int matid = lane >> 3, lrow = lane & 7;

    for (int kt = 0; kt < KITERS; kt++) {
        const int s = kt % NSTG;
        cp_wait2();
        __syncthreads();
        if (kt + 3 < KITERS) load_stage(kt + 3, (kt + 3) % NSTG);

        const uint32_t sa = sbase + s*STG;
        #pragma unroll
        for (int h = 0; h < 2; h++) {          // two k16 halves of BK=32
            const int cbase = h*2;
            uint32_t ah[4][4];
            #pragma unroll
            for (int mt = 0; mt < 4; mt++) {
                int m = wm*64 + mt*16 + ((matid & 1) ? 8 : 0) + lrow;
                int c = cbase + (matid >> 1);
                ldmx4(ah[mt], sa + SA_H + sw_off(m, c));
            }
            uint32_t bf[2][4];
            #pragma unroll
            for (int np = 0; np < 2; np++) {
                int n = wn*32 + np*16 + ((matid >> 1) ? 8 : 0) + lrow;
                int c = cbase + (matid & 1);
                ldmx4(bf[np], sa + SB_H + sw_off(n, c));
            }
            #pragma unroll
            for (int mt = 0; mt < 4; mt++)
                #pragma unroll
                for (int nt = 0; nt < 4; nt++)
                    mma16816(acc[mt][nt], ah[mt], &bf[nt >> 1][(nt & 1)*2]);
        }
    }

    // epilogue: write fp16 pairs
    const int mrow = wm*64 + (lane >> 2);
    const int ncol = wn*32 + (lane & 3)*2;
    #pragma unroll
    for (int nt = 0; nt < 4; nt++) {
        const int col = ncol + nt*8;
        const float b0 = bias[n0 + col], b1 = bias[n0 + col + 1];
        #pragma unroll
        for (int mt = 0; mt < 4; mt++) {
            __half* o = g_projh + ((size_t)stepi*BT + m0 + mrow + mt*16)*CC + n0 + col;
            *reinterpret_cast<__half2*>(o) =
                __floats2half2_rn(acc[mt][nt][0] + b0, acc[mt][nt][1] + b1);
            *reinterpret_cast<__half2*>(o + 8*CC) =
                __floats2half2_rn(acc[mt][nt][2] + b0, acc[mt][nt][3] + b1);
        }
    }
}

// ============================ logits dot kernel ============================
// One block per (b, t2). Only the 11 shared targets go through smem (16.9KB
// -> high occupancy); each warp loads its private proj rows straight from
// gmem. Warp w handles steps i = w, w+4, w+8.
__global__ __launch_bounds__(128) void dot2_kernel(
    const int* __restrict__ neg, float* __restrict__ outp)
{
    __shared__ uint2 sT[11*192];
    const int b  = blockIdx.y;
    const int t2 = blockIdx.x + 1;        // 1..1023
    const int tid = threadIdx.x;
    const int nvalid = (t2 < STEPS) ? t2 : STEPS;

    const uint2* yT2 = reinterpret_cast<const uint2*>(g_yTh);
    const uint2* pj2 = reinterpret_cast<const uint2*>(g_projh);

    for (int idx = tid; idx < 11*192; idx += 128) {
        int row = idx / 192, q = idx - row*192;
        int src = (row == 0) ? (b*TT + t2) : neg[b*(NNEG*TT) + (row-1)*TT + t2];
        sT[idx] = __ldg(&yT2[(size_t)src*192 + q]);
    }
    __syncthreads();

    const int wid = tid >> 5, lane = tid & 31;
    bool act[3];
    const uint2* prow[3];
    #pragma unroll
    for (int s = 0; s < 3; s++) {
        const int i = wid + s*4;
        act[s] = (i < nvalid);
        const int t = act[s] ? (t2 - 1 - i) : 0;
        prow[s] = pj2 + ((size_t)i*BT + (size_t)b*TT + t)*192;
    }

    float acc[3][COPIES];
    #pragma unroll
    for (int s = 0; s < 3; s++)
        #pragma unroll
        for (int n = 0; n < COPIES; n++) acc[s][n] = 0.f;

    #pragma unroll
    for (int it = 0; it < 6; it++) {
        const int q = lane + it*32;
        float4 tv[COPIES];
        #pragma unroll
        for (int n = 0; n < COPIES; n++) {
            uint2 tw = sT[n*192 + q];
            float2 t0 = __half22float2(*reinterpret_cast<__half2*>(&tw.x));
            float2 t1 = __half22float2(*reinterpret_cast<__half2*>(&tw.y));
            tv[n] = make_float4(t0.x, t0.y, t1.x, t1.y);
        }
        #pragma unroll
        for (int s = 0; s < 3; s++) {
            if (act[s]) {
                uint2 pw = __ldg(prow[s] + q);
                float2 f0 = __half22float2(*reinterpret_cast<__half2*>(&pw.x));
                float2 f1 = __half22float2(*reinterpret_cast<__half2*>(&pw.y));
                #pragma unroll
                for (int n = 0; n < COPIES; n++)
                    acc[s][n] += f0.x*tv[n].x + f0.y*tv[n].y + f1.x*tv[n].z + f1.y*tv[n].w;
            }
        }
    }

    #pragma unroll
    for (int s = 0; s < 3; s++) {
        const int i = wid + s*4;
        if (i >= nvalid) continue;
        #pragma unroll
        for (int n = 0; n < COPIES; n++)
            #pragma unroll
            for (int sh = 16; sh > 0; sh >>= 1)
                acc[s][n] += __shfl_xor_sync(0xffffffffu, acc[s][n], sh);
        if (lane == 0) {
            const int t = t2 - 1 - i;
            const int off = 16*(1023*i - (i*(i-1))/2);
            float* o = outp + (size_t)(off + t*BB + b)*COPIES;
            #pragma unroll
            for (int n = 0; n < COPIES; n++) o[n] = acc[s][n];
        }
    }
}

// ============================ host ============================
extern "C" void kernel_launch(void* const* d_in, const int* in_sizes, int n_in,
                              void* d_out, int out_size) {
    const float* x    = (const float*)d_in[0];
    const float* y    = (const float*)d_in[1];
    const float* W    = (const float*)d_in[2];
    const float* bias = (const float*)d_in[3];
    const int*   neg  = (const int*)d_in[4];
    float* out = (float*)d_out;

    int total_rows = 0;
    for (int i = 0; i < STEPS; i++) total_rows += (TT - 1 - i) * BB;  // 195360
    size_t npred = (size_t)total_rows * COPIES;

    if ((size_t)out_size > npred)
        cudaMemsetAsync((char*)d_out + npred * 4, 0, ((size_t)out_size - npred) * 4);

    static bool attr_set = false;
    if (!attr_set) {
        cudaFuncSetAttribute(gemm_hmma_kernel,
                             cudaFuncAttributeMaxDynamicSharedMemorySize, SMEM_GEMM);
        attr_set = true;
    }

    {   // fused x+y transpose -> fp16
        dim3 g(TT/32, CC/32, BB), blk(32, 8);
        pack_xy_kernel<<<g, blk>>>(x, y);
    }
    {   // W pack (fp16, coalesced smem transpose)
        dim3 g(CC/32, CC/32), blk(32, 8);
        pack_w_kernel<<<g, blk>>>(W);
    }
    {   // HMMA GEMM
        dim3 g(CC/BN, BT/BM, STEPS);   // (6, 128, 12)
        gemm_hmma_kernel<<<g, 256, SMEM_GEMM>>>(bias);
    }
    {   // logits
        dim3 g(TT-1, BB);              // (1023, 16)
        dot2_kernel<<<g, 128>>>(neg, out);
    }
}